// round 1
// baseline (speedup 1.0000x reference)
#include <cuda_runtime.h>
#include <math.h>

#define D      128
#define B_MAX  4096
#define NCLS   64

// ---------------- device scratch (no allocations allowed) ----------------
__device__ float  g_mag[B_MAX];
__device__ float  g_nes[B_MAX];
__device__ int    g_lab[B_MAX];
__device__ int    g_ccnt[NCLS];
__device__ int    g_cidx[NCLS * B_MAX];
__device__ double g_sum;

// ---------------- k0: zero scratch, detect int32 vs int64 labels ----------
__global__ void k0_prep(const int* __restrict__ tw, int B) {
    __shared__ int s_any;
    int tid = threadIdx.x;
    if (tid == 0) s_any = 0;
    __syncthreads();
    // If labels are int64 (values < 64), every odd 32-bit word of the first B
    // words is zero. If int32, those words are labels (all-zero ~impossible).
    int any = 0;
    for (int i = tid; i < B / 2; i += blockDim.x) any |= tw[2 * i + 1];
    if (any) atomicOr(&s_any, 1);
    __syncthreads();
    int is64 = (s_any == 0);
    for (int i = tid; i < B; i += blockDim.x) {
        g_lab[i] = is64 ? tw[2 * i] : tw[i];
        g_nes[i] = 0.0f;
    }
    if (tid < NCLS) g_ccnt[tid] = 0;
    if (tid == 0) g_sum = 0.0;
}

// ---------------- k1: row magnitudes + per-class index lists --------------
__global__ __launch_bounds__(256) void k1_mag(const float* __restrict__ score, int B) {
    int warp = threadIdx.x >> 5, lane = threadIdx.x & 31;
    int row = blockIdx.x * 8 + warp;
    if (row >= B) return;
    float4 v = *reinterpret_cast<const float4*>(&score[(size_t)row * D + lane * 4]);
    float s = v.x * v.x + v.y * v.y + v.z * v.z + v.w * v.w;
    s += __shfl_xor_sync(0xffffffffu, s, 16);
    s += __shfl_xor_sync(0xffffffffu, s, 8);
    s += __shfl_xor_sync(0xffffffffu, s, 4);
    s += __shfl_xor_sync(0xffffffffu, s, 2);
    s += __shfl_xor_sync(0xffffffffu, s, 1);
    if (lane == 0) {
        g_mag[row] = s;
        int c = g_lab[row];
        int p = atomicAdd(&g_ccnt[c], 1);
        g_cidx[c * B_MAX + p] = row;
    }
}

// ---------------- k2: symmetric tiled Gram + fused exp row/col sums -------
// Grid (B/128, B/128); blocks with by > bx exit (upper triangle only).
// Tile contributes row-sums to nes[i] always; col-sums to nes[j] iff by<bx.
__global__ __launch_bounds__(256) void k2_nes(const float* __restrict__ score,
                                              const float* __restrict__ alpha_p,
                                              int B) {
    int bx = blockIdx.x, by = blockIdx.y;
    if (by > bx) return;

    // k-transposed smem: As[k][row], pad 132 (16B-aligned rows, 4-way STS max)
    __shared__ float As[32][132];
    __shared__ float Bs[32][132];

    int tid = threadIdx.x;
    int tx = tid & 15, ty = tid >> 4;
    int rb = by * 128, cb = bx * 128;

    float acc[8][8];
#pragma unroll
    for (int m = 0; m < 8; m++)
#pragma unroll
        for (int n = 0; n < 8; n++) acc[m][n] = 0.0f;

    int lrow0 = tid >> 5;  // warp id 0..7
    int lk = tid & 31;     // lane = k within chunk -> coalesced 128B gmem reads

    for (int kc = 0; kc < D; kc += 32) {
        __syncthreads();
#pragma unroll
        for (int i = 0; i < 16; i++) {
            int row = lrow0 + i * 8;
            As[lk][row] = score[(size_t)(rb + row) * D + kc + lk];
            Bs[lk][row] = score[(size_t)(cb + row) * D + kc + lk];
        }
        __syncthreads();
#pragma unroll 8
        for (int k = 0; k < 32; k++) {
            float4 a0 = *reinterpret_cast<const float4*>(&As[k][ty * 8]);
            float4 a1 = *reinterpret_cast<const float4*>(&As[k][ty * 8 + 4]);
            float4 b0 = *reinterpret_cast<const float4*>(&Bs[k][tx * 8]);
            float4 b1 = *reinterpret_cast<const float4*>(&Bs[k][tx * 8 + 4]);
            float a[8] = {a0.x, a0.y, a0.z, a0.w, a1.x, a1.y, a1.z, a1.w};
            float b[8] = {b0.x, b0.y, b0.z, b0.w, b1.x, b1.y, b1.z, b1.w};
#pragma unroll
            for (int m = 0; m < 8; m++)
#pragma unroll
                for (int n = 0; n < 8; n++)
                    acc[m][n] = fmaf(a[m], b[n], acc[m][n]);
        }
    }

    // ---- epilogue: dist -> exp(alpha - dist) for negative pairs ----
    float alpha = __ldg(alpha_p);
    int gi0 = rb + ty * 8, gj0 = cb + tx * 8;
    float mi[8], mj[8];
    int li[8], lj[8];
#pragma unroll
    for (int m = 0; m < 8; m++) { mi[m] = g_mag[gi0 + m]; li[m] = g_lab[gi0 + m]; }
#pragma unroll
    for (int n = 0; n < 8; n++) { mj[n] = g_mag[gj0 + n]; lj[n] = g_lab[gj0 + n]; }

    float rsum[8], csum[8];
#pragma unroll
    for (int m = 0; m < 8; m++) rsum[m] = 0.0f;
#pragma unroll
    for (int n = 0; n < 8; n++) csum[n] = 0.0f;

#pragma unroll
    for (int m = 0; m < 8; m++) {
#pragma unroll
        for (int n = 0; n < 8; n++) {
            float d2 = fmaf(-2.0f, acc[m][n], mi[m] + mj[n]);
            float dist = sqrtf(fmaxf(d2, 0.0f));
            if (li[m] != lj[n]) {
                float e = __expf(alpha - dist);
                rsum[m] += e;
                csum[n] += e;
            }
        }
    }

    // row sums: reduce across tx (16 lanes within the warp half)
#pragma unroll
    for (int m = 0; m < 8; m++) {
        float v = rsum[m];
        v += __shfl_xor_sync(0xffffffffu, v, 1);
        v += __shfl_xor_sync(0xffffffffu, v, 2);
        v += __shfl_xor_sync(0xffffffffu, v, 4);
        v += __shfl_xor_sync(0xffffffffu, v, 8);
        if (tx == 0) atomicAdd(&g_nes[gi0 + m], v);
    }

    // column sums (only for strictly-off-diagonal blocks; symmetry credit)
    if (by != bx) {
        __syncthreads();  // done reading As; reuse as reduction buffer
        float* cr = &As[0][0];  // needs 16*128 = 2048 floats (< 32*132)
#pragma unroll
        for (int n = 0; n < 8; n++) cr[ty * 128 + tx * 8 + n] = csum[n];
        __syncthreads();
        if (tid < 128) {
            float s = 0.0f;
#pragma unroll
            for (int t = 0; t < 16; t++) s += cr[t * 128 + tid];
            atomicAdd(&g_nes[cb + tid], s);
        }
    }
}

// ---------------- k3: positive pairs, one warp per pair -------------------
__global__ __launch_bounds__(256) void k3_pos(const float* __restrict__ score, int B) {
    int c = blockIdx.x >> 4;                                    // 16 blocks/class
    int wid = ((blockIdx.x & 15) << 3) + (threadIdx.x >> 5);    // 0..127
    int lane = threadIdx.x & 31;
    int m = g_ccnt[c];
    long long P = (long long)m * (m - 1) / 2;
    const int* idx = &g_cidx[c * B_MAX];

    double wsum = 0.0;
    for (long long p = wid; p < P; p += 128) {
        // decode triangular index: pairs (x, y), 0 <= x < y < m
        int y = (int)((1.0 + sqrt(1.0 + 8.0 * (double)p)) * 0.5);
        while ((long long)y * (y - 1) / 2 > p) y--;
        while ((long long)(y + 1) * y / 2 <= p) y++;
        int x = (int)(p - (long long)y * (y - 1) / 2);
        int ia = idx[x], ib = idx[y];

        float4 va = *reinterpret_cast<const float4*>(&score[(size_t)ia * D + lane * 4]);
        float4 vb = *reinterpret_cast<const float4*>(&score[(size_t)ib * D + lane * 4]);
        float dot = va.x * vb.x + va.y * vb.y + va.z * vb.z + va.w * vb.w;
        dot += __shfl_xor_sync(0xffffffffu, dot, 16);
        dot += __shfl_xor_sync(0xffffffffu, dot, 8);
        dot += __shfl_xor_sync(0xffffffffu, dot, 4);
        dot += __shfl_xor_sync(0xffffffffu, dot, 2);
        dot += __shfl_xor_sync(0xffffffffu, dot, 1);

        if (lane == 0) {
            float d2 = fmaf(-2.0f, dot, g_mag[ia] + g_mag[ib]);
            float dist = sqrtf(fmaxf(d2, 0.0f));
            float l = __logf(g_nes[ia] + g_nes[ib]) + dist;
            if (l > 0.0f) wsum += (double)l * (double)l;
        }
    }
    if (lane == 0) atomicAdd(&g_sum, wsum);
}

// ---------------- k4: finalize --------------------------------------------
__global__ void k4_fin(float* out) {
    long long cnt = 0;
    for (int c = 0; c < NCLS; c++) {
        long long mc = g_ccnt[c];
        cnt += mc * (mc - 1) / 2;
    }
    out[0] = (float)(g_sum / (2.0 * (double)cnt));
}

// ---------------- launch ---------------------------------------------------
extern "C" void kernel_launch(void* const* d_in, const int* in_sizes, int n_in,
                              void* d_out, int out_size) {
    const float* score = (const float*)d_in[0];
    const int*   tgt   = (const int*)d_in[1];   // int32 or int64; detected on device
    const float* alpha = (const float*)d_in[2];
    float* out = (float*)d_out;
    int B = in_sizes[1];  // 4096

    k0_prep<<<1, 256>>>(tgt, B);
    k1_mag<<<B / 8, 256>>>(score, B);
    dim3 g2(B / 128, B / 128);
    k2_nes<<<g2, 256>>>(score, alpha, B);
    k3_pos<<<NCLS * 16, 256>>>(score, B);
    k4_fin<<<1, 1>>>(out);
}

// round 2
// speedup vs baseline: 1.8448x; 1.8448x over previous
#include <cuda_runtime.h>
#include <math.h>

#define D      128
#define B_MAX  4096
#define NCLS   64
#define PCAP   (1 << 19)   // 512k positive-pair capacity (expect ~129k)

// ---------------- device scratch (no allocations allowed) ----------------
__device__ float  g_mag[B_MAX];
__device__ float  g_nes[B_MAX];
__device__ int    g_lab[B_MAX];
__device__ int    g_ccnt[NCLS];
__device__ double g_sum;
__device__ int    g_pcnt;
__device__ int    g_pi[PCAP];
__device__ int    g_pj[PCAP];
__device__ float  g_pd[PCAP];

// ---------------- f32x2 helpers -------------------------------------------
__device__ __forceinline__ unsigned long long pack2(float x, float y) {
    unsigned long long r;
    asm("mov.b64 %0, {%1, %2};" : "=l"(r) : "f"(x), "f"(y));
    return r;
}
__device__ __forceinline__ void fma2(unsigned long long& d,
                                     unsigned long long a,
                                     unsigned long long b) {
    asm("fma.rn.f32x2 %0, %1, %2, %0;" : "+l"(d) : "l"(a), "l"(b));
}
__device__ __forceinline__ void unpack2(unsigned long long v, float& x, float& y) {
    asm("mov.b64 {%0, %1}, %2;" : "=f"(x), "=f"(y) : "l"(v));
}

// ---------------- k0: zero scratch, detect int32 vs int64 labels ----------
__global__ void k0_prep(const int* __restrict__ tw, int B) {
    __shared__ int s_any;
    int tid = threadIdx.x;
    if (tid == 0) s_any = 0;
    __syncthreads();
    int any = 0;
    for (int i = tid; i < B / 2; i += blockDim.x) any |= tw[2 * i + 1];
    if (any) atomicOr(&s_any, 1);
    __syncthreads();
    int is64 = (s_any == 0);
    for (int i = tid; i < B; i += blockDim.x) {
        g_lab[i] = is64 ? tw[2 * i] : tw[i];
        g_nes[i] = 0.0f;
    }
    if (tid < NCLS) g_ccnt[tid] = 0;
    if (tid == 0) { g_sum = 0.0; g_pcnt = 0; }
}

// ---------------- k1: row magnitudes + class counts ------------------------
__global__ __launch_bounds__(256) void k1_mag(const float* __restrict__ score, int B) {
    int warp = threadIdx.x >> 5, lane = threadIdx.x & 31;
    int row = blockIdx.x * 8 + warp;
    if (row >= B) return;
    float4 v = *reinterpret_cast<const float4*>(&score[(size_t)row * D + lane * 4]);
    float s = v.x * v.x + v.y * v.y + v.z * v.z + v.w * v.w;
    s += __shfl_xor_sync(0xffffffffu, s, 16);
    s += __shfl_xor_sync(0xffffffffu, s, 8);
    s += __shfl_xor_sync(0xffffffffu, s, 4);
    s += __shfl_xor_sync(0xffffffffu, s, 2);
    s += __shfl_xor_sync(0xffffffffu, s, 1);
    if (lane == 0) {
        g_mag[row] = s;
        atomicAdd(&g_ccnt[g_lab[row]], 1);
    }
}

// ---------------- k2: symmetric tiled Gram, FFMA2 core ---------------------
// exp row/col sums into g_nes; positive-pair (i,j,dist) recorded compactly.
__global__ __launch_bounds__(256) void k2_nes(const float* __restrict__ score,
                                              const float* __restrict__ alpha_p,
                                              int B) {
    int bx = blockIdx.x, by = blockIdx.y;
    if (by > bx) return;

    __shared__ float As[32][132];
    __shared__ float Bs[32][132];

    int tid = threadIdx.x;
    int tx = tid & 15, ty = tid >> 4;
    int rb = by * 128, cb = bx * 128;

    unsigned long long acc2[8][4];
#pragma unroll
    for (int m = 0; m < 8; m++)
#pragma unroll
        for (int n = 0; n < 4; n++) acc2[m][n] = pack2(0.0f, 0.0f);

    int lrow0 = tid >> 5;
    int lk = tid & 31;

    for (int kc = 0; kc < D; kc += 32) {
        __syncthreads();
#pragma unroll
        for (int i = 0; i < 16; i++) {
            int row = lrow0 + i * 8;
            As[lk][row] = score[(size_t)(rb + row) * D + kc + lk];
            Bs[lk][row] = score[(size_t)(cb + row) * D + kc + lk];
        }
        __syncthreads();
#pragma unroll 4
        for (int k = 0; k < 32; k++) {
            float4 a0 = *reinterpret_cast<const float4*>(&As[k][ty * 8]);
            float4 a1 = *reinterpret_cast<const float4*>(&As[k][ty * 8 + 4]);
            float4 b0 = *reinterpret_cast<const float4*>(&Bs[k][tx * 8]);
            float4 b1 = *reinterpret_cast<const float4*>(&Bs[k][tx * 8 + 4]);
            unsigned long long bb[4] = {pack2(b0.x, b0.y), pack2(b0.z, b0.w),
                                        pack2(b1.x, b1.y), pack2(b1.z, b1.w)};
            float av[8] = {a0.x, a0.y, a0.z, a0.w, a1.x, a1.y, a1.z, a1.w};
#pragma unroll
            for (int m = 0; m < 8; m++) {
                unsigned long long am = pack2(av[m], av[m]);
#pragma unroll
                for (int n = 0; n < 4; n++) fma2(acc2[m][n], am, bb[n]);
            }
        }
    }

    // unpack accumulators
    float acc[8][8];
#pragma unroll
    for (int m = 0; m < 8; m++)
#pragma unroll
        for (int n = 0; n < 4; n++)
            unpack2(acc2[m][n], acc[m][2 * n], acc[m][2 * n + 1]);

    // ---- epilogue ----
    float alpha = __ldg(alpha_p);
    int gi0 = rb + ty * 8, gj0 = cb + tx * 8;
    float mi[8], mj[8];
    int li[8], lj[8];
#pragma unroll
    for (int m = 0; m < 8; m++) { mi[m] = g_mag[gi0 + m]; li[m] = g_lab[gi0 + m]; }
#pragma unroll
    for (int n = 0; n < 8; n++) { mj[n] = g_mag[gj0 + n]; lj[n] = g_lab[gj0 + n]; }

    bool offdiag = (by != bx);
    float rsum[8], csum[8];
#pragma unroll
    for (int m = 0; m < 8; m++) rsum[m] = 0.0f;
#pragma unroll
    for (int n = 0; n < 8; n++) csum[n] = 0.0f;

    int npos = 0;  // positive pairs owned by this thread
#pragma unroll
    for (int m = 0; m < 8; m++) {
#pragma unroll
        for (int n = 0; n < 8; n++) {
            float d2 = fmaf(-2.0f, acc[m][n], mi[m] + mj[n]);
            float dist = sqrtf(fmaxf(d2, 0.0f));
            if (li[m] != lj[n]) {
                float e = __expf(alpha - dist);
                rsum[m] += e;
                csum[n] += e;
            } else if (offdiag || (gi0 + m) < (gj0 + n)) {
                npos++;
            }
        }
    }

    // warp-aggregated reservation of output slots
    if (__any_sync(0xffffffffu, npos)) {
        int lane = tid & 31;
        int incl = npos;
#pragma unroll
        for (int s = 1; s < 32; s <<= 1) {
            int v = __shfl_up_sync(0xffffffffu, incl, s);
            if (lane >= s) incl += v;
        }
        int base = 0;
        if (lane == 31) base = atomicAdd(&g_pcnt, incl);
        base = __shfl_sync(0xffffffffu, base, 31);
        int off = base + incl - npos;
        if (npos) {
#pragma unroll
            for (int m = 0; m < 8; m++) {
#pragma unroll
                for (int n = 0; n < 8; n++) {
                    if (li[m] == lj[n] && (offdiag || (gi0 + m) < (gj0 + n))) {
                        float d2 = fmaf(-2.0f, acc[m][n], mi[m] + mj[n]);
                        float dist = sqrtf(fmaxf(d2, 0.0f));
                        if (off < PCAP) {
                            g_pi[off] = gi0 + m;
                            g_pj[off] = gj0 + n;
                            g_pd[off] = dist;
                        }
                        off++;
                    }
                }
            }
        }
    }

    // row sums: reduce across tx (16 lanes within warp half)
#pragma unroll
    for (int m = 0; m < 8; m++) {
        float v = rsum[m];
        v += __shfl_xor_sync(0xffffffffu, v, 1);
        v += __shfl_xor_sync(0xffffffffu, v, 2);
        v += __shfl_xor_sync(0xffffffffu, v, 4);
        v += __shfl_xor_sync(0xffffffffu, v, 8);
        if (tx == 0) atomicAdd(&g_nes[gi0 + m], v);
    }

    // column sums (off-diagonal blocks only)
    if (offdiag) {
        __syncthreads();
        float* cr = &As[0][0];
#pragma unroll
        for (int n = 0; n < 8; n++) cr[ty * 128 + tx * 8 + n] = csum[n];
        __syncthreads();
        if (tid < 128) {
            float s = 0.0f;
#pragma unroll
            for (int t = 0; t < 16; t++) s += cr[t * 128 + tid];
            atomicAdd(&g_nes[cb + tid], s);
        }
    }
}

// ---------------- k3: positive-pair terms over recorded list ---------------
__global__ __launch_bounds__(256) void k3_terms() {
    int n = min(g_pcnt, PCAP);
    double wsum = 0.0;
    for (int p = blockIdx.x * blockDim.x + threadIdx.x; p < n;
         p += gridDim.x * blockDim.x) {
        int i = g_pi[p], j = g_pj[p];
        float l = __logf(g_nes[i] + g_nes[j]) + g_pd[p];
        if (l > 0.0f) wsum += (double)l * (double)l;
    }
    // warp reduce (double)
#pragma unroll
    for (int s = 16; s; s >>= 1)
        wsum += __shfl_xor_sync(0xffffffffu, wsum, s);
    if ((threadIdx.x & 31) == 0 && wsum != 0.0) atomicAdd(&g_sum, wsum);
}

// ---------------- k4: finalize ----------------------------------------------
__global__ void k4_fin(float* out) {
    long long cnt = 0;
    for (int c = 0; c < NCLS; c++) {
        long long mc = g_ccnt[c];
        cnt += mc * (mc - 1) / 2;
    }
    out[0] = (float)(g_sum / (2.0 * (double)cnt));
}

// ---------------- launch -----------------------------------------------------
extern "C" void kernel_launch(void* const* d_in, const int* in_sizes, int n_in,
                              void* d_out, int out_size) {
    const float* score = (const float*)d_in[0];
    const int*   tgt   = (const int*)d_in[1];   // int32 or int64, detected on device
    const float* alpha = (const float*)d_in[2];
    float* out = (float*)d_out;
    int B = in_sizes[1];  // 4096

    k0_prep<<<1, 256>>>(tgt, B);
    k1_mag<<<B / 8, 256>>>(score, B);
    dim3 g2(B / 128, B / 128);
    k2_nes<<<g2, 256>>>(score, alpha, B);
    k3_terms<<<256, 256>>>();
    k4_fin<<<1, 1>>>(out);
}

// round 4
// speedup vs baseline: 2.4545x; 1.3305x over previous
#include <cuda_runtime.h>
#include <cuda_bf16.h>
#include <math.h>
#include <stdint.h>

#define D      128
#define B_MAX  4096
#define NCLS   64
#define PCAP   (1 << 19)
#define PC     4096          // per-tile positive-pair buffer (worst case ~600 expected)

// ---------------- device scratch ----------------
__device__ __align__(16) __nv_bfloat16 g_hi[B_MAX * D];
__device__ __align__(16) __nv_bfloat16 g_lo[B_MAX * D];
__device__ float  g_mag[B_MAX];
__device__ float  g_nes[B_MAX];
__device__ int    g_lab[B_MAX];
__device__ int    g_ccnt[NCLS];
__device__ double g_sum;
__device__ int    g_pcnt;
__device__ int    g_pij[PCAP];
__device__ float  g_pd[PCAP];

// ---------------- helpers ----------------
__device__ __forceinline__ uint32_t smem_u32(const void* p) {
    uint32_t a;
    asm("{ .reg .u64 t; cvta.to.shared.u64 t, %1; cvt.u32.u64 %0, t; }" : "=r"(a) : "l"(p));
    return a;
}
#define LDSM4(r, a)                                                                     \
    asm volatile("ldmatrix.sync.aligned.m8n8.x4.shared.b16 {%0,%1,%2,%3}, [%4];"        \
                 : "=r"((r)[0]), "=r"((r)[1]), "=r"((r)[2]), "=r"((r)[3]) : "r"(a))
#define MMA16816(c, a, b0, b1)                                                          \
    asm volatile("mma.sync.aligned.m16n8k16.row.col.f32.bf16.bf16.f32 "                 \
                 "{%0,%1,%2,%3}, {%4,%5,%6,%7}, {%8,%9}, {%0,%1,%2,%3};"                \
                 : "+f"((c)[0]), "+f"((c)[1]), "+f"((c)[2]), "+f"((c)[3])               \
                 : "r"((a)[0]), "r"((a)[1]), "r"((a)[2]), "r"((a)[3]),                  \
                   "r"(b0), "r"(b1))

// ---------------- k0: init + label dtype detect ----------------
__global__ void k0_prep(const int* __restrict__ tw, int B) {
    __shared__ int s_any;
    int tid = threadIdx.x;
    if (tid == 0) s_any = 0;
    __syncthreads();
    int any = 0;
    for (int i = tid; i < B / 2; i += blockDim.x) any |= tw[2 * i + 1];
    if (any) atomicOr(&s_any, 1);
    __syncthreads();
    int is64 = (s_any == 0);
    for (int i = tid; i < B; i += blockDim.x) {
        g_lab[i] = is64 ? tw[2 * i] : tw[i];
        g_nes[i] = 0.0f;
    }
    if (tid < NCLS) g_ccnt[tid] = 0;
    if (tid == 0) { g_sum = 0.0; g_pcnt = 0; }
}

// ---------------- k1: mag + class counts + bf16 hi/lo split ----------------
__global__ __launch_bounds__(256) void k1_mag(const float* __restrict__ score, int B) {
    int warp = threadIdx.x >> 5, lane = threadIdx.x & 31;
    int row = blockIdx.x * 8 + warp;
    if (row >= B) return;
    float4 v = *reinterpret_cast<const float4*>(&score[(size_t)row * D + lane * 4]);

    float x[4] = {v.x, v.y, v.z, v.w};
    uint16_t h[4], l[4];
#pragma unroll
    for (int q = 0; q < 4; q++) {
        __nv_bfloat16 hb = __float2bfloat16_rn(x[q]);
        __nv_bfloat16 lb = __float2bfloat16_rn(x[q] - __bfloat162float(hb));
        h[q] = __bfloat16_as_ushort(hb);
        l[q] = __bfloat16_as_ushort(lb);
    }
    uint2 hp = make_uint2((uint32_t)h[1] << 16 | h[0], (uint32_t)h[3] << 16 | h[2]);
    uint2 lp = make_uint2((uint32_t)l[1] << 16 | l[0], (uint32_t)l[3] << 16 | l[2]);
    *reinterpret_cast<uint2*>(&g_hi[(size_t)row * D + lane * 4]) = hp;
    *reinterpret_cast<uint2*>(&g_lo[(size_t)row * D + lane * 4]) = lp;

    float s = v.x * v.x + v.y * v.y + v.z * v.z + v.w * v.w;
    s += __shfl_xor_sync(0xffffffffu, s, 16);
    s += __shfl_xor_sync(0xffffffffu, s, 8);
    s += __shfl_xor_sync(0xffffffffu, s, 4);
    s += __shfl_xor_sync(0xffffffffu, s, 2);
    s += __shfl_xor_sync(0xffffffffu, s, 1);
    if (lane == 0) {
        g_mag[row] = s;
        atomicAdd(&g_ccnt[g_lab[row]], 1);
    }
}

// ---------------- k2: HMMA split-bf16 Gram tile (triangle) ----------------
#define LDK   136                       // padded stride in bf16 elems (272 B rows)
#define TILEB (128 * LDK * 2)           // 34816 B per tile
#define OFF_AHI  0
#define OFF_ALO  (OFF_AHI + TILEB)
#define OFF_BHI  (OFF_ALO + TILEB)
#define OFF_BLO  (OFF_BHI + TILEB)
#define OFF_LABA (OFF_BLO + TILEB)
#define OFF_MAGA (OFF_LABA + 512)
#define OFF_LABB (OFF_MAGA + 512)
#define OFF_MAGB (OFF_LABB + 512)
#define OFF_RS   (OFF_MAGB + 512)
#define OFF_CS   (OFF_RS + 512)
#define OFF_CNT  (OFF_CS + 512)
#define OFF_BASE (OFF_CNT + 4)
#define OFF_PIJ  (OFF_CNT + 16)
#define OFF_PD   (OFF_PIJ + PC * 4)
#define SMEM_SZ  (OFF_PD + PC * 4)

__global__ __launch_bounds__(256, 1) void k2_mma(const float* __restrict__ alpha_p) {
    extern __shared__ char smem[];
    uint32_t sb = smem_u32(smem);
    int tid = threadIdx.x, wid = tid >> 5, lane = tid & 31;

    // triangular block decode: blocks (by <= bx)
    int p = blockIdx.x;
    int bx = (int)((sqrtf(8.0f * p + 1.0f) - 1.0f) * 0.5f);
    while ((bx + 1) * (bx + 2) / 2 <= p) bx++;
    while (bx * (bx + 1) / 2 > p) bx--;
    int by = p - bx * (bx + 1) / 2;
    int rb = by * 128, cb = bx * 128;
    bool offdiag = (bx != by);

    float* s_rs = reinterpret_cast<float*>(smem + OFF_RS);
    float* s_cs = reinterpret_cast<float*>(smem + OFF_CS);
    int* s_labA = reinterpret_cast<int*>(smem + OFF_LABA);
    float* s_magA = reinterpret_cast<float*>(smem + OFF_MAGA);
    int* s_labB = reinterpret_cast<int*>(smem + OFF_LABB);
    float* s_magB = reinterpret_cast<float*>(smem + OFF_MAGB);
    int* s_cnt = reinterpret_cast<int*>(smem + OFF_CNT);
    int* s_base = reinterpret_cast<int*>(smem + OFF_BASE);
    int* s_pij = reinterpret_cast<int*>(smem + OFF_PIJ);
    float* s_pd = reinterpret_cast<float*>(smem + OFF_PD);

    if (tid < 128) {
        s_labA[tid] = g_lab[rb + tid];
        s_magA[tid] = g_mag[rb + tid];
        s_labB[tid] = g_lab[cb + tid];
        s_magB[tid] = g_mag[cb + tid];
        s_rs[tid] = 0.0f;
        s_cs[tid] = 0.0f;
    }
    if (tid == 0) *s_cnt = 0;

    // load tiles: 128 rows x 16 chunks of 16B each, 4 tiles
    const uint4* ahi = reinterpret_cast<const uint4*>(&g_hi[(size_t)rb * D]);
    const uint4* alo = reinterpret_cast<const uint4*>(&g_lo[(size_t)rb * D]);
    const uint4* bhi = reinterpret_cast<const uint4*>(&g_hi[(size_t)cb * D]);
    const uint4* blo = reinterpret_cast<const uint4*>(&g_lo[(size_t)cb * D]);
#pragma unroll
    for (int it = 0; it < 8; it++) {
        int c = it * 256 + tid;            // 0..2047
        int row = c >> 4, kc = c & 15;
        uint32_t dst = (uint32_t)(row * LDK * 2 + kc * 16);
        *reinterpret_cast<uint4*>(smem + OFF_AHI + dst) = ahi[c];
        *reinterpret_cast<uint4*>(smem + OFF_ALO + dst) = alo[c];
        *reinterpret_cast<uint4*>(smem + OFF_BHI + dst) = bhi[c];
        *reinterpret_cast<uint4*>(smem + OFF_BLO + dst) = blo[c];
    }
    __syncthreads();

    // warp grid 2(M) x 4(N): warp tile 64x32
    int warp_m = wid & 1, warp_n = wid >> 1;
    float acc[4][4][4];
#pragma unroll
    for (int ma = 0; ma < 4; ma++)
#pragma unroll
        for (int na = 0; na < 4; na++)
#pragma unroll
            for (int q = 0; q < 4; q++) acc[ma][na][q] = 0.0f;

    uint32_t a_off = ((uint32_t)(warp_m * 64 + (lane & 7) + ((lane >> 3) & 1) * 8) * LDK +
                      (uint32_t)(lane >> 4) * 8) * 2;
    uint32_t b_off = ((uint32_t)(warp_n * 32 + (lane & 15)) * LDK +
                      (uint32_t)(lane >> 4) * 8) * 2;

#pragma unroll
    for (int pass = 0; pass < 3; pass++) {
        uint32_t sa = sb + (pass == 2 ? OFF_ALO : OFF_AHI) + a_off;
        uint32_t sB = sb + (pass == 1 ? OFF_BLO : OFF_BHI) + b_off;
#pragma unroll
        for (int ks = 0; ks < 8; ks++) {
            uint32_t ar[4][4], br[2][4];
#pragma unroll
            for (int ma = 0; ma < 4; ma++)
                LDSM4(ar[ma], sa + (uint32_t)(ma * 16 * LDK + ks * 16) * 2);
#pragma unroll
            for (int nb = 0; nb < 2; nb++)
                LDSM4(br[nb], sB + (uint32_t)(nb * 16 * LDK + ks * 16) * 2);
#pragma unroll
            for (int ma = 0; ma < 4; ma++)
#pragma unroll
                for (int na = 0; na < 4; na++)
                    MMA16816(acc[ma][na], ar[ma], br[na >> 1][na & 1], br[na >> 1][(na & 1) + 2]);
        }
    }

    // ---- epilogue ----
    float alpha = __ldg(alpha_p);
    float rsumv[4][2], csumv[4][2];
#pragma unroll
    for (int ma = 0; ma < 4; ma++) rsumv[ma][0] = rsumv[ma][1] = 0.0f;
#pragma unroll
    for (int na = 0; na < 4; na++) csumv[na][0] = csumv[na][1] = 0.0f;

#pragma unroll
    for (int ma = 0; ma < 4; ma++) {
        int r0 = warp_m * 64 + ma * 16 + (lane >> 2);
#pragma unroll
        for (int h = 0; h < 2; h++) {
            int r = r0 + h * 8;
            float mi = s_magA[r];
            int li = s_labA[r];
#pragma unroll
            for (int na = 0; na < 4; na++) {
                int c0 = warp_n * 32 + na * 8 + (lane & 3) * 2;
#pragma unroll
                for (int q = 0; q < 2; q++) {
                    int c = c0 + q;
                    float dot = acc[ma][na][h * 2 + q];
                    float d2 = fmaf(-2.0f, dot, mi + s_magB[c]);
                    float dist = sqrtf(fmaxf(d2, 0.0f));
                    if (li != s_labB[c]) {
                        float e = __expf(alpha - dist);
                        rsumv[ma][h] += e;
                        csumv[na][q] += e;
                    } else {
                        int gi = rb + r, gj = cb + c;
                        if (offdiag || gi < gj) {
                            int idx = atomicAdd(s_cnt, 1);
                            if (idx < PC) { s_pij[idx] = (gi << 12) | gj; s_pd[idx] = dist; }
                        }
                    }
                }
            }
        }
    }

    // reduce row sums across quad lanes (same row for lane&3 group)
#pragma unroll
    for (int ma = 0; ma < 4; ma++)
#pragma unroll
        for (int h = 0; h < 2; h++) {
            float v = rsumv[ma][h];
            v += __shfl_xor_sync(0xffffffffu, v, 1);
            v += __shfl_xor_sync(0xffffffffu, v, 2);
            if ((lane & 3) == 0)
                atomicAdd(&s_rs[warp_m * 64 + ma * 16 + (lane >> 2) + h * 8], v);
        }
    // reduce col sums across lanes sharing a column (lane>>2 varies)
    if (offdiag) {
#pragma unroll
        for (int na = 0; na < 4; na++)
#pragma unroll
            for (int q = 0; q < 2; q++) {
                float v = csumv[na][q];
                v += __shfl_xor_sync(0xffffffffu, v, 4);
                v += __shfl_xor_sync(0xffffffffu, v, 8);
                v += __shfl_xor_sync(0xffffffffu, v, 16);
                if (lane < 4)
                    atomicAdd(&s_cs[warp_n * 32 + na * 8 + (lane & 3) * 2 + q], v);
            }
    }

    __syncthreads();
    if (tid < 128) {
        atomicAdd(&g_nes[rb + tid], s_rs[tid]);
        if (offdiag) atomicAdd(&g_nes[cb + tid], s_cs[tid]);
    }
    int npair = min(*s_cnt, PC);
    if (tid == 0) *s_base = atomicAdd(&g_pcnt, npair);
    __syncthreads();
    int base = *s_base;
    for (int q = tid; q < npair; q += 256) {
        g_pij[base + q] = s_pij[q];
        g_pd[base + q] = s_pd[q];
    }
}

// ---------------- k3: positive-pair terms ----------------
__global__ __launch_bounds__(256) void k3_terms() {
    __shared__ double red[8];
    int n = min(g_pcnt, PCAP);
    double w = 0.0;
    for (int p = blockIdx.x * blockDim.x + threadIdx.x; p < n; p += gridDim.x * blockDim.x) {
        int ij = g_pij[p];
        int i = ij >> 12, j = ij & 4095;
        float l = __logf(g_nes[i] + g_nes[j]) + g_pd[p];
        if (l > 0.0f) w += (double)l * (double)l;
    }
#pragma unroll
    for (int s = 16; s; s >>= 1) w += __shfl_xor_sync(0xffffffffu, w, s);
    int wid = threadIdx.x >> 5;
    if ((threadIdx.x & 31) == 0) red[wid] = w;
    __syncthreads();
    if (threadIdx.x == 0) {
        double t = 0.0;
        for (int q = 0; q < 8; q++) t += red[q];
        if (t != 0.0) atomicAdd(&g_sum, t);
    }
}

// ---------------- k4: finalize ----------------
__global__ void k4_fin(float* out) {
    long long cnt = 0;
    for (int c = 0; c < NCLS; c++) {
        long long mc = g_ccnt[c];
        cnt += mc * (mc - 1) / 2;
    }
    out[0] = (float)(g_sum / (2.0 * (double)cnt));
}

// ---------------- launch ----------------
extern "C" void kernel_launch(void* const* d_in, const int* in_sizes, int n_in,
                              void* d_out, int out_size) {
    const float* score = (const float*)d_in[0];
    const int*   tgt   = (const int*)d_in[1];
    const float* alpha = (const float*)d_in[2];
    float* out = (float*)d_out;
    int B = in_sizes[1];  // 4096

    cudaFuncSetAttribute(k2_mma, cudaFuncAttributeMaxDynamicSharedMemorySize, SMEM_SZ);

    k0_prep<<<1, 256>>>(tgt, B);
    k1_mag<<<B / 8, 256>>>(score, B);
    int nb = B / 128;
    int nblk = nb * (nb + 1) / 2;      // 528 triangular tiles
    k2_mma<<<nblk, 256, SMEM_SZ>>>(alpha);
    k3_terms<<<64, 256>>>();
    k4_fin<<<1, 1>>>(out);
}

// round 5
// speedup vs baseline: 3.1933x; 1.3010x over previous
#include <cuda_runtime.h>
#include <cuda_bf16.h>
#include <math.h>
#include <stdint.h>

#define D      128
#define B_MAX  4096
#define NCLS   64
#define PCAP   (1 << 19)
#define PC     1536          // per-tile positive-pair buffer (expected ~256)

// ---------------- device scratch ----------------
__device__ __align__(16) __nv_bfloat16 g_hi[B_MAX * D];
__device__ __align__(16) __nv_bfloat16 g_lo[B_MAX * D];
__device__ float  g_mag[B_MAX];
__device__ float  g_nes[B_MAX];
__device__ int    g_lab[B_MAX];
__device__ int    g_ccnt[NCLS];
__device__ double g_sum;
__device__ int    g_pcnt;
__device__ int    g_pij[PCAP];
__device__ float  g_pd[PCAP];

// ---------------- helpers ----------------
__device__ __forceinline__ uint32_t smem_u32(const void* p) {
    uint32_t a;
    asm("{ .reg .u64 t; cvta.to.shared.u64 t, %1; cvt.u32.u64 %0, t; }" : "=r"(a) : "l"(p));
    return a;
}
#define LDSM4(r, a)                                                                     \
    asm volatile("ldmatrix.sync.aligned.m8n8.x4.shared.b16 {%0,%1,%2,%3}, [%4];"        \
                 : "=r"((r)[0]), "=r"((r)[1]), "=r"((r)[2]), "=r"((r)[3]) : "r"(a))
#define MMA16816(c, a, b0, b1)                                                          \
    asm volatile("mma.sync.aligned.m16n8k16.row.col.f32.bf16.bf16.f32 "                 \
                 "{%0,%1,%2,%3}, {%4,%5,%6,%7}, {%8,%9}, {%0,%1,%2,%3};"                \
                 : "+f"((c)[0]), "+f"((c)[1]), "+f"((c)[2]), "+f"((c)[3])               \
                 : "r"((a)[0]), "r"((a)[1]), "r"((a)[2]), "r"((a)[3]),                  \
                   "r"(b0), "r"(b1))

// ---------------- k0: init + label dtype detect ----------------
__global__ void k0_prep(const int* __restrict__ tw, int B) {
    __shared__ int s_any;
    int tid = threadIdx.x;
    if (tid == 0) s_any = 0;
    __syncthreads();
    int any = 0;
    for (int i = tid; i < B / 2; i += blockDim.x) any |= tw[2 * i + 1];
    if (any) atomicOr(&s_any, 1);
    __syncthreads();
    int is64 = (s_any == 0);
    for (int i = tid; i < B; i += blockDim.x) {
        g_lab[i] = is64 ? tw[2 * i] : tw[i];
        g_nes[i] = 0.0f;
    }
    if (tid < NCLS) g_ccnt[tid] = 0;
    if (tid == 0) { g_sum = 0.0; g_pcnt = 0; }
}

// ---------------- k1: mag + class counts + bf16 hi/lo split ----------------
__global__ __launch_bounds__(256) void k1_mag(const float* __restrict__ score, int B) {
    int warp = threadIdx.x >> 5, lane = threadIdx.x & 31;
    int row = blockIdx.x * 8 + warp;
    if (row >= B) return;
    float4 v = *reinterpret_cast<const float4*>(&score[(size_t)row * D + lane * 4]);

    float x[4] = {v.x, v.y, v.z, v.w};
    uint16_t h[4], l[4];
#pragma unroll
    for (int q = 0; q < 4; q++) {
        __nv_bfloat16 hb = __float2bfloat16_rn(x[q]);
        __nv_bfloat16 lb = __float2bfloat16_rn(x[q] - __bfloat162float(hb));
        h[q] = __bfloat16_as_ushort(hb);
        l[q] = __bfloat16_as_ushort(lb);
    }
    uint2 hp = make_uint2((uint32_t)h[1] << 16 | h[0], (uint32_t)h[3] << 16 | h[2]);
    uint2 lp = make_uint2((uint32_t)l[1] << 16 | l[0], (uint32_t)l[3] << 16 | l[2]);
    *reinterpret_cast<uint2*>(&g_hi[(size_t)row * D + lane * 4]) = hp;
    *reinterpret_cast<uint2*>(&g_lo[(size_t)row * D + lane * 4]) = lp;

    float s = v.x * v.x + v.y * v.y + v.z * v.z + v.w * v.w;
    s += __shfl_xor_sync(0xffffffffu, s, 16);
    s += __shfl_xor_sync(0xffffffffu, s, 8);
    s += __shfl_xor_sync(0xffffffffu, s, 4);
    s += __shfl_xor_sync(0xffffffffu, s, 2);
    s += __shfl_xor_sync(0xffffffffu, s, 1);
    if (lane == 0) {
        g_mag[row] = s;
        atomicAdd(&g_ccnt[g_lab[row]], 1);
    }
}

// ---------------- k2: HMMA split-bf16 Gram tile (triangle, split-K) -------
#define KC    64                        // K-chunk (elems)
#define LDK   72                        // padded chunk stride in bf16 elems (144 B)
#define TILEB (128 * LDK * 2)           // 18432 B per chunk tile
#define OFF_AHI  0
#define OFF_ALO  (OFF_AHI + TILEB)
#define OFF_BHI  (OFF_ALO + TILEB)
#define OFF_BLO  (OFF_BHI + TILEB)
#define OFF_LABA (OFF_BLO + TILEB)
#define OFF_MAGA (OFF_LABA + 512)
#define OFF_LABB (OFF_MAGA + 512)
#define OFF_MAGB (OFF_LABB + 512)
#define OFF_RS   (OFF_MAGB + 512)
#define OFF_CS   (OFF_RS + 512)
#define OFF_CNT  (OFF_CS + 512)
#define OFF_BASE (OFF_CNT + 4)
#define OFF_PIJ  (OFF_CNT + 16)
#define OFF_PD   (OFF_PIJ + PC * 4)
#define SMEM_SZ  (OFF_PD + PC * 4)

__global__ __launch_bounds__(256, 2) void k2_mma(const float* __restrict__ alpha_p) {
    extern __shared__ char smem[];
    uint32_t sb = smem_u32(smem);
    int tid = threadIdx.x, wid = tid >> 5, lane = tid & 31;

    // triangular block decode: blocks (by <= bx)
    int p = blockIdx.x;
    int bx = (int)((sqrtf(8.0f * p + 1.0f) - 1.0f) * 0.5f);
    while ((bx + 1) * (bx + 2) / 2 <= p) bx++;
    while (bx * (bx + 1) / 2 > p) bx--;
    int by = p - bx * (bx + 1) / 2;
    int rb = by * 128, cb = bx * 128;
    bool offdiag = (bx != by);

    float* s_rs = reinterpret_cast<float*>(smem + OFF_RS);
    float* s_cs = reinterpret_cast<float*>(smem + OFF_CS);
    int* s_labA = reinterpret_cast<int*>(smem + OFF_LABA);
    float* s_magA = reinterpret_cast<float*>(smem + OFF_MAGA);
    int* s_labB = reinterpret_cast<int*>(smem + OFF_LABB);
    float* s_magB = reinterpret_cast<float*>(smem + OFF_MAGB);
    int* s_cnt = reinterpret_cast<int*>(smem + OFF_CNT);
    int* s_base = reinterpret_cast<int*>(smem + OFF_BASE);
    int* s_pij = reinterpret_cast<int*>(smem + OFF_PIJ);
    float* s_pd = reinterpret_cast<float*>(smem + OFF_PD);

    if (tid < 128) {
        s_labA[tid] = g_lab[rb + tid];
        s_magA[tid] = g_mag[rb + tid];
        s_labB[tid] = g_lab[cb + tid];
        s_magB[tid] = g_mag[cb + tid];
        s_rs[tid] = 0.0f;
        s_cs[tid] = 0.0f;
    }
    if (tid == 0) *s_cnt = 0;

    // warp grid 2(M) x 4(N): warp tile 64x32
    int warp_m = wid & 1, warp_n = wid >> 1;
    float acc[4][4][4];
#pragma unroll
    for (int ma = 0; ma < 4; ma++)
#pragma unroll
        for (int na = 0; na < 4; na++)
#pragma unroll
            for (int q = 0; q < 4; q++) acc[ma][na][q] = 0.0f;

    uint32_t a_off = ((uint32_t)(warp_m * 64 + (lane & 7) + ((lane >> 3) & 1) * 8) * LDK +
                      (uint32_t)(lane >> 4) * 8) * 2;
    uint32_t b_off = ((uint32_t)(warp_n * 32 + (lane & 15)) * LDK +
                      (uint32_t)(lane >> 4) * 8) * 2;

    for (int ch = 0; ch < 2; ch++) {
        int kb = ch * KC;  // k-chunk base in elems
        __syncthreads();   // prior-chunk MMA reads done before overwrite (and init phase)
        // load chunk: 128 rows x 8 chunks of 16B per tile, 4 tiles = 4096 uint4
        const uint4* ahi = reinterpret_cast<const uint4*>(&g_hi[(size_t)rb * D + kb]);
        const uint4* alo = reinterpret_cast<const uint4*>(&g_lo[(size_t)rb * D + kb]);
        const uint4* bhi = reinterpret_cast<const uint4*>(&g_hi[(size_t)cb * D + kb]);
        const uint4* blo = reinterpret_cast<const uint4*>(&g_lo[(size_t)cb * D + kb]);
#pragma unroll
        for (int it = 0; it < 4; it++) {
            int c = it * 256 + tid;                   // 0..1023
            int row = c >> 3, kc16 = c & 7;
            int src = row * (D / 8) + kc16;           // gmem uint4 index (row stride D/8)
            uint32_t dst = (uint32_t)(row * LDK * 2 + kc16 * 16);
            *reinterpret_cast<uint4*>(smem + OFF_AHI + dst) = ahi[src];
            *reinterpret_cast<uint4*>(smem + OFF_ALO + dst) = alo[src];
            *reinterpret_cast<uint4*>(smem + OFF_BHI + dst) = bhi[src];
            *reinterpret_cast<uint4*>(smem + OFF_BLO + dst) = blo[src];
        }
        __syncthreads();

#pragma unroll
        for (int pass = 0; pass < 3; pass++) {
            uint32_t sa = sb + (pass == 2 ? OFF_ALO : OFF_AHI) + a_off;
            uint32_t sB = sb + (pass == 1 ? OFF_BLO : OFF_BHI) + b_off;
#pragma unroll
            for (int ks = 0; ks < 4; ks++) {
                uint32_t ar[4][4], br[2][4];
#pragma unroll
                for (int ma = 0; ma < 4; ma++)
                    LDSM4(ar[ma], sa + (uint32_t)(ma * 16 * LDK + ks * 16) * 2);
#pragma unroll
                for (int nb = 0; nb < 2; nb++)
                    LDSM4(br[nb], sB + (uint32_t)(nb * 16 * LDK + ks * 16) * 2);
#pragma unroll
                for (int ma = 0; ma < 4; ma++)
#pragma unroll
                    for (int na = 0; na < 4; na++)
                        MMA16816(acc[ma][na], ar[ma], br[na >> 1][na & 1], br[na >> 1][(na & 1) + 2]);
            }
        }
    }

    // ---- epilogue ----
    float alpha = __ldg(alpha_p);
    float rsumv[4][2], csumv[4][2];
#pragma unroll
    for (int ma = 0; ma < 4; ma++) rsumv[ma][0] = rsumv[ma][1] = 0.0f;
#pragma unroll
    for (int na = 0; na < 4; na++) csumv[na][0] = csumv[na][1] = 0.0f;

#pragma unroll
    for (int ma = 0; ma < 4; ma++) {
        int r0 = warp_m * 64 + ma * 16 + (lane >> 2);
#pragma unroll
        for (int h = 0; h < 2; h++) {
            int r = r0 + h * 8;
            float mi = s_magA[r];
            int li = s_labA[r];
#pragma unroll
            for (int na = 0; na < 4; na++) {
                int c0 = warp_n * 32 + na * 8 + (lane & 3) * 2;
#pragma unroll
                for (int q = 0; q < 2; q++) {
                    int c = c0 + q;
                    float dot = acc[ma][na][h * 2 + q];
                    float d2 = fmaf(-2.0f, dot, mi + s_magB[c]);
                    float dist = sqrtf(fmaxf(d2, 0.0f));
                    if (li != s_labB[c]) {
                        float e = __expf(alpha - dist);
                        rsumv[ma][h] += e;
                        csumv[na][q] += e;
                    } else {
                        int gi = rb + r, gj = cb + c;
                        if (offdiag || gi < gj) {
                            int idx = atomicAdd(s_cnt, 1);
                            if (idx < PC) { s_pij[idx] = (gi << 12) | gj; s_pd[idx] = dist; }
                        }
                    }
                }
            }
        }
    }

    // reduce row sums across quad lanes
#pragma unroll
    for (int ma = 0; ma < 4; ma++)
#pragma unroll
        for (int h = 0; h < 2; h++) {
            float v = rsumv[ma][h];
            v += __shfl_xor_sync(0xffffffffu, v, 1);
            v += __shfl_xor_sync(0xffffffffu, v, 2);
            if ((lane & 3) == 0)
                atomicAdd(&s_rs[warp_m * 64 + ma * 16 + (lane >> 2) + h * 8], v);
        }
    // reduce col sums across lanes sharing a column
    if (offdiag) {
#pragma unroll
        for (int na = 0; na < 4; na++)
#pragma unroll
            for (int q = 0; q < 2; q++) {
                float v = csumv[na][q];
                v += __shfl_xor_sync(0xffffffffu, v, 4);
                v += __shfl_xor_sync(0xffffffffu, v, 8);
                v += __shfl_xor_sync(0xffffffffu, v, 16);
                if (lane < 4)
                    atomicAdd(&s_cs[warp_n * 32 + na * 8 + (lane & 3) * 2 + q], v);
            }
    }

    __syncthreads();
    if (tid < 128) {
        atomicAdd(&g_nes[rb + tid], s_rs[tid]);
        if (offdiag) atomicAdd(&g_nes[cb + tid], s_cs[tid]);
    }
    int npair = min(*s_cnt, PC);
    if (tid == 0) *s_base = atomicAdd(&g_pcnt, npair);
    __syncthreads();
    int base = *s_base;
    for (int q = tid; q < npair; q += 256) {
        if (base + q < PCAP) {
            g_pij[base + q] = s_pij[q];
            g_pd[base + q] = s_pd[q];
        }
    }
}

// ---------------- k3: positive-pair terms ----------------
__global__ __launch_bounds__(256) void k3_terms() {
    __shared__ double red[8];
    int n = min(g_pcnt, PCAP);
    double w = 0.0;
    for (int p = blockIdx.x * blockDim.x + threadIdx.x; p < n; p += gridDim.x * blockDim.x) {
        int ij = g_pij[p];
        int i = ij >> 12, j = ij & 4095;
        float l = __logf(g_nes[i] + g_nes[j]) + g_pd[p];
        if (l > 0.0f) w += (double)l * (double)l;
    }
#pragma unroll
    for (int s = 16; s; s >>= 1) w += __shfl_xor_sync(0xffffffffu, w, s);
    int wid = threadIdx.x >> 5;
    if ((threadIdx.x & 31) == 0) red[wid] = w;
    __syncthreads();
    if (threadIdx.x == 0) {
        double t = 0.0;
        for (int q = 0; q < 8; q++) t += red[q];
        if (t != 0.0) atomicAdd(&g_sum, t);
    }
}

// ---------------- k4: finalize ----------------
__global__ void k4_fin(float* out) {
    long long cnt = 0;
    for (int c = 0; c < NCLS; c++) {
        long long mc = g_ccnt[c];
        cnt += mc * (mc - 1) / 2;
    }
    out[0] = (float)(g_sum / (2.0 * (double)cnt));
}

// ---------------- launch ----------------
extern "C" void kernel_launch(void* const* d_in, const int* in_sizes, int n_in,
                              void* d_out, int out_size) {
    const float* score = (const float*)d_in[0];
    const int*   tgt   = (const int*)d_in[1];
    const float* alpha = (const float*)d_in[2];
    float* out = (float*)d_out;
    int B = in_sizes[1];  // 4096

    cudaFuncSetAttribute(k2_mma, cudaFuncAttributeMaxDynamicSharedMemorySize, SMEM_SZ);

    k0_prep<<<1, 256>>>(tgt, B);
    k1_mag<<<B / 8, 256>>>(score, B);
    int nb = B / 128;
    int nblk = nb * (nb + 1) / 2;      // 528 triangular tiles
    k2_mma<<<nblk, 256, SMEM_SZ>>>(alpha);
    k3_terms<<<296, 256>>>();
    k4_fin<<<1, 1>>>(out);
}

// round 7
// speedup vs baseline: 4.4579x; 1.3960x over previous
#include <cuda_runtime.h>
#include <cuda_fp16.h>
#include <math.h>
#include <stdint.h>

#define D      128
#define B_MAX  4096
#define NCLS   64
#define PCAP   (1 << 19)
#define PC     1536          // per-tile positive-pair buffer (expected ~256)

// ---------------- device scratch ----------------
__device__ __align__(16) __half g_h16[B_MAX * D];
__device__ float  g_mag[B_MAX];
__device__ float  g_nes[B_MAX];
__device__ int    g_lab[B_MAX];
__device__ int    g_ccnt[NCLS];
__device__ double g_sum;
__device__ int    g_pcnt;
__device__ int    g_pij[PCAP];
__device__ float  g_pd[PCAP];

// ---------------- helpers ----------------
__device__ __forceinline__ uint32_t smem_u32(const void* p) {
    uint32_t a;
    asm("{ .reg .u64 t; cvta.to.shared.u64 t, %1; cvt.u32.u64 %0, t; }" : "=r"(a) : "l"(p));
    return a;
}
__device__ __forceinline__ uint32_t h2_bits(__half2 h) {
    return *reinterpret_cast<uint32_t*>(&h);
}
#define LDSM4(r, a)                                                                     \
    asm volatile("ldmatrix.sync.aligned.m8n8.x4.shared.b16 {%0,%1,%2,%3}, [%4];"        \
                 : "=r"((r)[0]), "=r"((r)[1]), "=r"((r)[2]), "=r"((r)[3]) : "r"(a))
#define MMA16816(c, a, b0, b1)                                                          \
    asm volatile("mma.sync.aligned.m16n8k16.row.col.f32.f16.f16.f32 "                   \
                 "{%0,%1,%2,%3}, {%4,%5,%6,%7}, {%8,%9}, {%0,%1,%2,%3};"                \
                 : "+f"((c)[0]), "+f"((c)[1]), "+f"((c)[2]), "+f"((c)[3])               \
                 : "r"((a)[0]), "r"((a)[1]), "r"((a)[2]), "r"((a)[3]),                  \
                   "r"(b0), "r"(b1))

// ---------------- k0: init + label dtype detect ----------------
__global__ void k0_prep(const int* __restrict__ tw, int B) {
    __shared__ int s_any;
    int tid = threadIdx.x;
    if (tid == 0) s_any = 0;
    __syncthreads();
    int any = 0;
    for (int i = tid; i < B / 2; i += blockDim.x) any |= tw[2 * i + 1];
    if (any) atomicOr(&s_any, 1);
    __syncthreads();
    int is64 = (s_any == 0);
    for (int i = tid; i < B; i += blockDim.x) {
        g_lab[i] = is64 ? tw[2 * i] : tw[i];
        g_nes[i] = 0.0f;
    }
    if (tid < NCLS) g_ccnt[tid] = 0;
    if (tid == 0) { g_sum = 0.0; g_pcnt = 0; }
}

// ---------------- k1: mag + class counts + fp16 copy ----------------
__global__ __launch_bounds__(256) void k1_mag(const float* __restrict__ score, int B) {
    int warp = threadIdx.x >> 5, lane = threadIdx.x & 31;
    int row = blockIdx.x * 8 + warp;
    if (row >= B) return;
    float4 v = *reinterpret_cast<const float4*>(&score[(size_t)row * D + lane * 4]);

    uint32_t p0 = h2_bits(__floats2half2_rn(v.x, v.y));
    uint32_t p1 = h2_bits(__floats2half2_rn(v.z, v.w));
    *reinterpret_cast<uint2*>(&g_h16[(size_t)row * D + lane * 4]) = make_uint2(p0, p1);

    float s = v.x * v.x + v.y * v.y + v.z * v.z + v.w * v.w;
    s += __shfl_xor_sync(0xffffffffu, s, 16);
    s += __shfl_xor_sync(0xffffffffu, s, 8);
    s += __shfl_xor_sync(0xffffffffu, s, 4);
    s += __shfl_xor_sync(0xffffffffu, s, 2);
    s += __shfl_xor_sync(0xffffffffu, s, 1);
    if (lane == 0) {
        g_mag[row] = s;
        atomicAdd(&g_ccnt[g_lab[row]], 1);
    }
}

// ---------------- k2: fp16 HMMA Gram tile (triangle, full-K) --------------
#define LDK   136                       // padded stride in fp16 elems (272 B rows)
#define TILEB (128 * LDK * 2)           // 34816 B per tile
#define OFF_A    0
#define OFF_B    (OFF_A + TILEB)
#define OFF_LABA (OFF_B + TILEB)
#define OFF_MAGA (OFF_LABA + 512)
#define OFF_LABB (OFF_MAGA + 512)
#define OFF_MAGB (OFF_LABB + 512)
#define OFF_RS   (OFF_MAGB + 512)
#define OFF_CS   (OFF_RS + 512)
#define OFF_CNT  (OFF_CS + 512)
#define OFF_BASE (OFF_CNT + 4)
#define OFF_PIJ  (OFF_CNT + 16)
#define OFF_PD   (OFF_PIJ + PC * 4)
#define SMEM_SZ  (OFF_PD + PC * 4)

__global__ __launch_bounds__(256, 2) void k2_mma(const float* __restrict__ alpha_p) {
    extern __shared__ char smem[];
    uint32_t sb = smem_u32(smem);
    int tid = threadIdx.x, wid = tid >> 5, lane = tid & 31;

    // triangular block decode: blocks (by <= bx)
    int p = blockIdx.x;
    int bx = (int)((sqrtf(8.0f * p + 1.0f) - 1.0f) * 0.5f);
    while ((bx + 1) * (bx + 2) / 2 <= p) bx++;
    while (bx * (bx + 1) / 2 > p) bx--;
    int by = p - bx * (bx + 1) / 2;
    int rb = by * 128, cb = bx * 128;
    bool offdiag = (bx != by);

    float* s_rs = reinterpret_cast<float*>(smem + OFF_RS);
    float* s_cs = reinterpret_cast<float*>(smem + OFF_CS);
    int* s_labA = reinterpret_cast<int*>(smem + OFF_LABA);
    float* s_magA = reinterpret_cast<float*>(smem + OFF_MAGA);
    int* s_labB = reinterpret_cast<int*>(smem + OFF_LABB);
    float* s_magB = reinterpret_cast<float*>(smem + OFF_MAGB);
    int* s_cnt = reinterpret_cast<int*>(smem + OFF_CNT);
    int* s_base = reinterpret_cast<int*>(smem + OFF_BASE);
    int* s_pij = reinterpret_cast<int*>(smem + OFF_PIJ);
    float* s_pd = reinterpret_cast<float*>(smem + OFF_PD);

    if (tid < 128) {
        s_labA[tid] = g_lab[rb + tid];
        s_magA[tid] = g_mag[rb + tid];
        s_labB[tid] = g_lab[cb + tid];
        s_magB[tid] = g_mag[cb + tid];
        s_rs[tid] = 0.0f;
        s_cs[tid] = 0.0f;
    }
    if (tid == 0) *s_cnt = 0;

    // load both tiles: 128 rows x 16 chunks of 16B each
    const uint4* ga = reinterpret_cast<const uint4*>(&g_h16[(size_t)rb * D]);
    const uint4* gb = reinterpret_cast<const uint4*>(&g_h16[(size_t)cb * D]);
#pragma unroll
    for (int it = 0; it < 8; it++) {
        int c = it * 256 + tid;            // 0..2047
        int row = c >> 4, kc = c & 15;
        uint32_t dst = (uint32_t)(row * (LDK * 2) + kc * 16);
        *reinterpret_cast<uint4*>(smem + OFF_A + dst) = ga[c];
        *reinterpret_cast<uint4*>(smem + OFF_B + dst) = gb[c];
    }
    __syncthreads();

    // warp grid 2(M) x 4(N): warp tile 64x32
    int warp_m = wid & 1, warp_n = wid >> 1;
    float acc[4][4][4];
#pragma unroll
    for (int ma = 0; ma < 4; ma++)
#pragma unroll
        for (int na = 0; na < 4; na++)
#pragma unroll
            for (int q = 0; q < 4; q++) acc[ma][na][q] = 0.0f;

    uint32_t sa = sb + OFF_A +
        ((uint32_t)(warp_m * 64 + (lane & 7) + ((lane >> 3) & 1) * 8) * LDK +
         (uint32_t)(lane >> 4) * 8) * 2;
    uint32_t sB = sb + OFF_B +
        ((uint32_t)(warp_n * 32 + (lane & 15)) * LDK +
         (uint32_t)(lane >> 4) * 8) * 2;

#pragma unroll
    for (int ks = 0; ks < 8; ks++) {
        uint32_t ar[4][4], br[2][4];
#pragma unroll
        for (int ma = 0; ma < 4; ma++)
            LDSM4(ar[ma], sa + (uint32_t)(ma * 16 * LDK + ks * 16) * 2);
#pragma unroll
        for (int nb = 0; nb < 2; nb++)
            LDSM4(br[nb], sB + (uint32_t)(nb * 16 * LDK + ks * 16) * 2);
#pragma unroll
        for (int ma = 0; ma < 4; ma++)
#pragma unroll
            for (int na = 0; na < 4; na++)
                MMA16816(acc[ma][na], ar[ma], br[na >> 1][na & 1], br[na >> 1][(na & 1) + 2]);
    }

    // ---- epilogue ----
    float alpha = __ldg(alpha_p);
    float rsumv[4][2], csumv[4][2];
#pragma unroll
    for (int ma = 0; ma < 4; ma++) rsumv[ma][0] = rsumv[ma][1] = 0.0f;
#pragma unroll
    for (int na = 0; na < 4; na++) csumv[na][0] = csumv[na][1] = 0.0f;

#pragma unroll
    for (int ma = 0; ma < 4; ma++) {
        int r0 = warp_m * 64 + ma * 16 + (lane >> 2);
#pragma unroll
        for (int h = 0; h < 2; h++) {
            int r = r0 + h * 8;
            float mi = s_magA[r];
            int li = s_labA[r];
#pragma unroll
            for (int na = 0; na < 4; na++) {
                int c0 = warp_n * 32 + na * 8 + (lane & 3) * 2;
#pragma unroll
                for (int q = 0; q < 2; q++) {
                    int c = c0 + q;
                    float dot = acc[ma][na][h * 2 + q];
                    float d2 = fmaf(-2.0f, dot, mi + s_magB[c]);
                    float dist = sqrtf(fmaxf(d2, 0.0f));
                    if (li != s_labB[c]) {
                        float e = __expf(alpha - dist);
                        rsumv[ma][h] += e;
                        csumv[na][q] += e;
                    } else {
                        int gi = rb + r, gj = cb + c;
                        if (offdiag || gi < gj) {
                            int idx = atomicAdd(s_cnt, 1);
                            if (idx < PC) { s_pij[idx] = (gi << 12) | gj; s_pd[idx] = dist; }
                        }
                    }
                }
            }
        }
    }

    // reduce row sums across quad lanes
#pragma unroll
    for (int ma = 0; ma < 4; ma++)
#pragma unroll
        for (int h = 0; h < 2; h++) {
            float v = rsumv[ma][h];
            v += __shfl_xor_sync(0xffffffffu, v, 1);
            v += __shfl_xor_sync(0xffffffffu, v, 2);
            if ((lane & 3) == 0)
                atomicAdd(&s_rs[warp_m * 64 + ma * 16 + (lane >> 2) + h * 8], v);
        }
    // reduce col sums across lanes sharing a column
    if (offdiag) {
#pragma unroll
        for (int na = 0; na < 4; na++)
#pragma unroll
            for (int q = 0; q < 2; q++) {
                float v = csumv[na][q];
                v += __shfl_xor_sync(0xffffffffu, v, 4);
                v += __shfl_xor_sync(0xffffffffu, v, 8);
                v += __shfl_xor_sync(0xffffffffu, v, 16);
                if (lane < 4)
                    atomicAdd(&s_cs[warp_n * 32 + na * 8 + (lane & 3) * 2 + q], v);
            }
    }

    __syncthreads();
    if (tid < 128) {
        atomicAdd(&g_nes[rb + tid], s_rs[tid]);
        if (offdiag) atomicAdd(&g_nes[cb + tid], s_cs[tid]);
    }
    int npair = min(*s_cnt, PC);
    if (tid == 0) *s_base = atomicAdd(&g_pcnt, npair);
    __syncthreads();
    int base = *s_base;
    for (int q = tid; q < npair; q += 256) {
        if (base + q < PCAP) {
            g_pij[base + q] = s_pij[q];
            g_pd[base + q] = s_pd[q];
        }
    }
}

// ---------------- k3: positive-pair terms ----------------
__global__ __launch_bounds__(256) void k3_terms() {
    __shared__ double red[8];
    int n = min(g_pcnt, PCAP);
    double w = 0.0;
    for (int p = blockIdx.x * blockDim.x + threadIdx.x; p < n; p += gridDim.x * blockDim.x) {
        int ij = g_pij[p];
        int i = ij >> 12, j = ij & 4095;
        float l = __logf(g_nes[i] + g_nes[j]) + g_pd[p];
        if (l > 0.0f) w += (double)l * (double)l;
    }
#pragma unroll
    for (int s = 16; s; s >>= 1) w += __shfl_xor_sync(0xffffffffu, w, s);
    int wid = threadIdx.x >> 5;
    if ((threadIdx.x & 31) == 0) red[wid] = w;
    __syncthreads();
    if (threadIdx.x == 0) {
        double t = 0.0;
        for (int q = 0; q < 8; q++) t += red[q];
        if (t != 0.0) atomicAdd(&g_sum, t);
    }
}

// ---------------- k4: finalize ----------------
__global__ void k4_fin(float* out) {
    long long cnt = 0;
    for (int c = 0; c < NCLS; c++) {
        long long mc = g_ccnt[c];
        cnt += mc * (mc - 1) / 2;
    }
    out[0] = (float)(g_sum / (2.0 * (double)cnt));
}

// ---------------- launch ----------------
extern "C" void kernel_launch(void* const* d_in, const int* in_sizes, int n_in,
                              void* d_out, int out_size) {
    const float* score = (const float*)d_in[0];
    const int*   tgt   = (const int*)d_in[1];
    const float* alpha = (const float*)d_in[2];
    float* out = (float*)d_out;
    int B = in_sizes[1];  // 4096

    cudaFuncSetAttribute(k2_mma, cudaFuncAttributeMaxDynamicSharedMemorySize, SMEM_SZ);

    k0_prep<<<1, 256>>>(tgt, B);
    k1_mag<<<B / 8, 256>>>(score, B);
    int nb = B / 128;
    int nblk = nb * (nb + 1) / 2;      // 528 triangular tiles
    k2_mma<<<nblk, 256, SMEM_SZ>>>(alpha);
    k3_terms<<<296, 256>>>();
    k4_fin<<<1, 1>>>(out);
}

// round 8
// speedup vs baseline: 5.1128x; 1.1469x over previous
#include <cuda_runtime.h>
#include <cuda_fp16.h>
#include <math.h>
#include <stdint.h>

#define D      128
#define B_MAX  4096
#define NCLS   64
#define PCAP   (1 << 19)
#define PC     1536          // per-tile positive-pair buffer (expected ~256)

// ---------------- device scratch ----------------
__device__ __align__(16) __half g_h16[B_MAX * D];
__device__ float  g_mag[B_MAX];
__device__ float  g_nes[B_MAX];
__device__ int    g_lab[B_MAX];
__device__ int    g_ccnt[NCLS];
__device__ double g_sum;
__device__ int    g_pcnt;
__device__ int    g_pij[PCAP];
__device__ float  g_pd[PCAP];

// ---------------- helpers ----------------
__device__ __forceinline__ uint32_t smem_u32(const void* p) {
    uint32_t a;
    asm("{ .reg .u64 t; cvta.to.shared.u64 t, %1; cvt.u32.u64 %0, t; }" : "=r"(a) : "l"(p));
    return a;
}
__device__ __forceinline__ uint32_t h2_bits(__half2 h) {
    return *reinterpret_cast<uint32_t*>(&h);
}
__device__ __forceinline__ float fsqrt_fast(float x) {
    float r;
    asm("sqrt.approx.f32 %0, %1;" : "=f"(r) : "f"(x));
    return r;
}
#define LDSM4(r, a)                                                                     \
    asm volatile("ldmatrix.sync.aligned.m8n8.x4.shared.b16 {%0,%1,%2,%3}, [%4];"        \
                 : "=r"((r)[0]), "=r"((r)[1]), "=r"((r)[2]), "=r"((r)[3]) : "r"(a))
#define MMA16816(c, a, b0, b1)                                                          \
    asm volatile("mma.sync.aligned.m16n8k16.row.col.f32.f16.f16.f32 "                   \
                 "{%0,%1,%2,%3}, {%4,%5,%6,%7}, {%8,%9}, {%0,%1,%2,%3};"                \
                 : "+f"((c)[0]), "+f"((c)[1]), "+f"((c)[2]), "+f"((c)[3])               \
                 : "r"((a)[0]), "r"((a)[1]), "r"((a)[2]), "r"((a)[3]),                  \
                   "r"(b0), "r"(b1))

// ---------------- k0: init + label dtype detect ----------------
__global__ void k0_prep(const int* __restrict__ tw, int B) {
    __shared__ int s_any;
    int tid = threadIdx.x;
    if (tid == 0) s_any = 0;
    __syncthreads();
    int any = 0;
    for (int i = tid; i < B / 2; i += blockDim.x) any |= tw[2 * i + 1];
    if (any) atomicOr(&s_any, 1);
    __syncthreads();
    int is64 = (s_any == 0);
    for (int i = tid; i < B; i += blockDim.x) {
        g_lab[i] = is64 ? tw[2 * i] : tw[i];
        g_nes[i] = 0.0f;
    }
    if (tid < NCLS) g_ccnt[tid] = 0;
    if (tid == 0) { g_sum = 0.0; g_pcnt = 0; }
}

// ---------------- k1: mag + class counts + fp16 copy ----------------
__global__ __launch_bounds__(256) void k1_mag(const float* __restrict__ score, int B) {
    int warp = threadIdx.x >> 5, lane = threadIdx.x & 31;
    int row = blockIdx.x * 8 + warp;
    if (row >= B) return;
    float4 v = *reinterpret_cast<const float4*>(&score[(size_t)row * D + lane * 4]);

    uint32_t p0 = h2_bits(__floats2half2_rn(v.x, v.y));
    uint32_t p1 = h2_bits(__floats2half2_rn(v.z, v.w));
    *reinterpret_cast<uint2*>(&g_h16[(size_t)row * D + lane * 4]) = make_uint2(p0, p1);

    float s = v.x * v.x + v.y * v.y + v.z * v.z + v.w * v.w;
    s += __shfl_xor_sync(0xffffffffu, s, 16);
    s += __shfl_xor_sync(0xffffffffu, s, 8);
    s += __shfl_xor_sync(0xffffffffu, s, 4);
    s += __shfl_xor_sync(0xffffffffu, s, 2);
    s += __shfl_xor_sync(0xffffffffu, s, 1);
    if (lane == 0) {
        g_mag[row] = s;
        atomicAdd(&g_ccnt[g_lab[row]], 1);
    }
}

// ---------------- k2: fp16 HMMA Gram tile (triangle, full-K) --------------
#define LDK   136                       // padded stride in fp16 elems (272 B rows)
#define TILEB (128 * LDK * 2)           // 34816 B per tile
#define OFF_A    0
#define OFF_B    (OFF_A + TILEB)
#define OFF_LABA (OFF_B + TILEB)
#define OFF_MAGA (OFF_LABA + 512)
#define OFF_LABB (OFF_MAGA + 512)
#define OFF_MAGB (OFF_LABB + 512)
#define OFF_CNT  (OFF_MAGB + 512)
#define OFF_BASE (OFF_CNT + 4)
#define OFF_PIJ  (OFF_CNT + 16)
#define OFF_PD   (OFF_PIJ + PC * 4)
#define SMEM_SZ  (OFF_PD + PC * 4)

__global__ __launch_bounds__(256, 2) void k2_mma(const float* __restrict__ alpha_p) {
    extern __shared__ char smem[];
    uint32_t sb = smem_u32(smem);
    int tid = threadIdx.x, wid = tid >> 5, lane = tid & 31;

    // triangular block decode: blocks (by <= bx)
    int p = blockIdx.x;
    int bx = (int)((sqrtf(8.0f * p + 1.0f) - 1.0f) * 0.5f);
    while ((bx + 1) * (bx + 2) / 2 <= p) bx++;
    while (bx * (bx + 1) / 2 > p) bx--;
    int by = p - bx * (bx + 1) / 2;
    int rb = by * 128, cb = bx * 128;
    bool offdiag = (bx != by);

    int* s_labA = reinterpret_cast<int*>(smem + OFF_LABA);
    float* s_magA = reinterpret_cast<float*>(smem + OFF_MAGA);
    int* s_labB = reinterpret_cast<int*>(smem + OFF_LABB);
    float* s_magB = reinterpret_cast<float*>(smem + OFF_MAGB);
    int* s_cnt = reinterpret_cast<int*>(smem + OFF_CNT);
    int* s_base = reinterpret_cast<int*>(smem + OFF_BASE);
    int* s_pij = reinterpret_cast<int*>(smem + OFF_PIJ);
    float* s_pd = reinterpret_cast<float*>(smem + OFF_PD);

    if (tid < 128) {
        s_labA[tid] = g_lab[rb + tid];
        s_magA[tid] = g_mag[rb + tid];
        s_labB[tid] = g_lab[cb + tid];
        s_magB[tid] = g_mag[cb + tid];
    }
    if (tid == 0) *s_cnt = 0;

    // load both tiles: 128 rows x 16 chunks of 16B each
    const uint4* ga = reinterpret_cast<const uint4*>(&g_h16[(size_t)rb * D]);
    const uint4* gb = reinterpret_cast<const uint4*>(&g_h16[(size_t)cb * D]);
#pragma unroll
    for (int it = 0; it < 8; it++) {
        int c = it * 256 + tid;            // 0..2047
        int row = c >> 4, kc = c & 15;
        uint32_t dst = (uint32_t)(row * (LDK * 2) + kc * 16);
        *reinterpret_cast<uint4*>(smem + OFF_A + dst) = ga[c];
        *reinterpret_cast<uint4*>(smem + OFF_B + dst) = gb[c];
    }
    __syncthreads();

    // warp grid 2(M) x 4(N): warp tile 64x32
    int warp_m = wid & 1, warp_n = wid >> 1;
    float acc[4][4][4];
#pragma unroll
    for (int ma = 0; ma < 4; ma++)
#pragma unroll
        for (int na = 0; na < 4; na++)
#pragma unroll
            for (int q = 0; q < 4; q++) acc[ma][na][q] = 0.0f;

    uint32_t sa = sb + OFF_A +
        ((uint32_t)(warp_m * 64 + (lane & 7) + ((lane >> 3) & 1) * 8) * LDK +
         (uint32_t)(lane >> 4) * 8) * 2;
    uint32_t sB = sb + OFF_B +
        ((uint32_t)(warp_n * 32 + (lane & 15)) * LDK +
         (uint32_t)(lane >> 4) * 8) * 2;

#pragma unroll
    for (int ks = 0; ks < 8; ks++) {
        uint32_t ar[4][4], br[2][4];
#pragma unroll
        for (int ma = 0; ma < 4; ma++)
            LDSM4(ar[ma], sa + (uint32_t)(ma * 16 * LDK + ks * 16) * 2);
#pragma unroll
        for (int nb = 0; nb < 2; nb++)
            LDSM4(br[nb], sB + (uint32_t)(nb * 16 * LDK + ks * 16) * 2);
#pragma unroll
        for (int ma = 0; ma < 4; ma++)
#pragma unroll
            for (int na = 0; na < 4; na++)
                MMA16816(acc[ma][na], ar[ma], br[na >> 1][na & 1], br[na >> 1][(na & 1) + 2]);
    }

    // ---- epilogue: all labels/mags hoisted to registers ----
    float alpha = __ldg(alpha_p);
    int ljv[8];
    float mjv[8];
#pragma unroll
    for (int na = 0; na < 4; na++)
#pragma unroll
        for (int q = 0; q < 2; q++) {
            int c = warp_n * 32 + na * 8 + (lane & 3) * 2 + q;
            ljv[na * 2 + q] = s_labB[c];
            mjv[na * 2 + q] = s_magB[c];
        }
    int liv[8];
    float miv[8];
#pragma unroll
    for (int ma = 0; ma < 4; ma++)
#pragma unroll
        for (int h = 0; h < 2; h++) {
            int r = warp_m * 64 + ma * 16 + (lane >> 2) + h * 8;
            liv[ma * 2 + h] = s_labA[r];
            miv[ma * 2 + h] = s_magA[r];
        }

    float csum[8];
#pragma unroll
    for (int q = 0; q < 8; q++) csum[q] = 0.0f;

#pragma unroll
    for (int ma = 0; ma < 4; ma++) {
#pragma unroll
        for (int h = 0; h < 2; h++) {
            float mi = miv[ma * 2 + h];
            int li = liv[ma * 2 + h];
            float rs = 0.0f;
#pragma unroll
            for (int na = 0; na < 4; na++) {
#pragma unroll
                for (int q = 0; q < 2; q++) {
                    float dot = acc[ma][na][h * 2 + q];
                    float d2 = fmaf(-2.0f, dot, mi + mjv[na * 2 + q]);
                    float dist = fsqrt_fast(fmaxf(d2, 0.0f));
                    if (li != ljv[na * 2 + q]) {
                        float e = __expf(alpha - dist);
                        rs += e;
                        csum[na * 2 + q] += e;
                    } else {
                        int gi = rb + warp_m * 64 + ma * 16 + (lane >> 2) + h * 8;
                        int gj = cb + warp_n * 32 + na * 8 + (lane & 3) * 2 + q;
                        if (offdiag || gi < gj) {
                            int idx = atomicAdd(s_cnt, 1);
                            if (idx < PC) { s_pij[idx] = (gi << 12) | gj; s_pd[idx] = dist; }
                        }
                    }
                }
            }
            // row-sum: reduce across the 4 lanes of the quad, atomic to gmem
            rs += __shfl_xor_sync(0xffffffffu, rs, 1);
            rs += __shfl_xor_sync(0xffffffffu, rs, 2);
            if ((lane & 3) == 0)
                atomicAdd(&g_nes[rb + warp_m * 64 + ma * 16 + (lane >> 2) + h * 8], rs);
        }
    }

    // col sums: reduce across lane>>2, atomic to gmem (off-diagonal only)
    if (offdiag) {
#pragma unroll
        for (int na = 0; na < 4; na++)
#pragma unroll
            for (int q = 0; q < 2; q++) {
                float v = csum[na * 2 + q];
                v += __shfl_xor_sync(0xffffffffu, v, 4);
                v += __shfl_xor_sync(0xffffffffu, v, 8);
                v += __shfl_xor_sync(0xffffffffu, v, 16);
                if (lane < 4)
                    atomicAdd(&g_nes[cb + warp_n * 32 + na * 8 + (lane & 3) * 2 + q], v);
            }
    }

    // ---- flush positive pairs ----
    __syncthreads();
    int npair = min(*s_cnt, PC);
    if (tid == 0) *s_base = atomicAdd(&g_pcnt, npair);
    __syncthreads();
    int base = *s_base;
    for (int q = tid; q < npair; q += 256) {
        if (base + q < PCAP) {
            g_pij[base + q] = s_pij[q];
            g_pd[base + q] = s_pd[q];
        }
    }
}

// ---------------- k3: positive-pair terms ----------------
__global__ __launch_bounds__(128) void k3_terms() {
    __shared__ double red[4];
    int n = min(g_pcnt, PCAP);
    double w = 0.0;
    for (int p = blockIdx.x * blockDim.x + threadIdx.x; p < n; p += gridDim.x * blockDim.x) {
        int ij = g_pij[p];
        int i = ij >> 12, j = ij & 4095;
        float l = __logf(g_nes[i] + g_nes[j]) + g_pd[p];
        if (l > 0.0f) w += (double)l * (double)l;
    }
#pragma unroll
    for (int s = 16; s; s >>= 1) w += __shfl_xor_sync(0xffffffffu, w, s);
    int wid = threadIdx.x >> 5;
    if ((threadIdx.x & 31) == 0) red[wid] = w;
    __syncthreads();
    if (threadIdx.x == 0) {
        double t = red[0] + red[1] + red[2] + red[3];
        if (t != 0.0) atomicAdd(&g_sum, t);
    }
}

// ---------------- k4: finalize ----------------
__global__ void k4_fin(float* out) {
    long long cnt = 0;
    for (int c = 0; c < NCLS; c++) {
        long long mc = g_ccnt[c];
        cnt += mc * (mc - 1) / 2;
    }
    out[0] = (float)(g_sum / (2.0 * (double)cnt));
}

// ---------------- launch ----------------
extern "C" void kernel_launch(void* const* d_in, const int* in_sizes, int n_in,
                              void* d_out, int out_size) {
    const float* score = (const float*)d_in[0];
    const int*   tgt   = (const int*)d_in[1];
    const float* alpha = (const float*)d_in[2];
    float* out = (float*)d_out;
    int B = in_sizes[1];  // 4096

    cudaFuncSetAttribute(k2_mma, cudaFuncAttributeMaxDynamicSharedMemorySize, SMEM_SZ);
    cudaFuncSetAttribute(k2_mma, cudaFuncAttributePreferredSharedMemoryCarveout, 100);

    k0_prep<<<1, 256>>>(tgt, B);
    k1_mag<<<B / 8, 256>>>(score, B);
    int nb = B / 128;
    int nblk = nb * (nb + 1) / 2;      // 528 triangular tiles
    k2_mma<<<nblk, 256, SMEM_SZ>>>(alpha);
    k3_terms<<<592, 128>>>();
    k4_fin<<<1, 1>>>(out);
}

// round 9
// speedup vs baseline: 5.5288x; 1.0814x over previous
#include <cuda_runtime.h>
#include <cuda_fp16.h>
#include <math.h>
#include <stdint.h>

#define D      128
#define B_MAX  4096
#define PCAP   (1 << 19)
#define PC     1536
#define NTILE  528           // 32*33/2 triangular 128x128 tiles
#define NCTA   296           // 2 per SM

// ---------------- device scratch ----------------
__device__ __align__(16) __half g_h16[B_MAX * D];
__device__ float  g_mag[B_MAX];
__device__ float  g_nes[B_MAX];
__device__ int    g_lab[B_MAX];
__device__ double g_part[160];
__device__ int    g_pcnt;
__device__ int    g_tile;
__device__ int    g_pij[PCAP];
__device__ float  g_pd[PCAP];

// ---------------- helpers ----------------
__device__ __forceinline__ uint32_t smem_u32(const void* p) {
    uint32_t a;
    asm("{ .reg .u64 t; cvta.to.shared.u64 t, %1; cvt.u32.u64 %0, t; }" : "=r"(a) : "l"(p));
    return a;
}
__device__ __forceinline__ uint32_t h2_bits(__half2 h) {
    return *reinterpret_cast<uint32_t*>(&h);
}
__device__ __forceinline__ float fsqrt_fast(float x) {
    float r;
    asm("sqrt.approx.f32 %0, %1;" : "=f"(r) : "f"(x));
    return r;
}
__device__ __forceinline__ void cpa16(uint32_t dst, const void* src) {
    asm volatile("cp.async.cg.shared.global [%0], [%1], 16;" :: "r"(dst), "l"(src));
}
#define CP_COMMIT() asm volatile("cp.async.commit_group;" ::: "memory")
#define CP_WAIT0()  asm volatile("cp.async.wait_group 0;" ::: "memory")
#define LDSM4(r, a)                                                                     \
    asm volatile("ldmatrix.sync.aligned.m8n8.x4.shared.b16 {%0,%1,%2,%3}, [%4];"        \
                 : "=r"((r)[0]), "=r"((r)[1]), "=r"((r)[2]), "=r"((r)[3]) : "r"(a))
#define MMA16816(c, a, b0, b1)                                                          \
    asm volatile("mma.sync.aligned.m16n8k16.row.col.f32.f16.f16.f32 "                   \
                 "{%0,%1,%2,%3}, {%4,%5,%6,%7}, {%8,%9}, {%0,%1,%2,%3};"                \
                 : "+f"((c)[0]), "+f"((c)[1]), "+f"((c)[2]), "+f"((c)[3])               \
                 : "r"((a)[0]), "r"((a)[1]), "r"((a)[2]), "r"((a)[3]),                  \
                   "r"(b0), "r"(b1))

__device__ __forceinline__ void tile_decode(int p, int& bx, int& by) {
    bx = (int)((sqrtf(8.0f * p + 1.0f) - 1.0f) * 0.5f);
    while ((bx + 1) * (bx + 2) / 2 <= p) bx++;
    while (bx * (bx + 1) / 2 > p) bx--;
    by = p - bx * (bx + 1) / 2;
}

// ---------------- k1: is64 detect + labels + mags + fp16 + init -----------
__global__ __launch_bounds__(256) void k1_prep(const float* __restrict__ score,
                                               const int* __restrict__ tw, int B) {
    __shared__ int s_any;
    int tid = threadIdx.x;
    if (tid == 0) s_any = 0;
    __syncthreads();
    int any = 0;
    for (int i = tid; i < B / 2; i += 256) any |= tw[2 * i + 1];
    if (any) atomicOr(&s_any, 1);
    __syncthreads();
    int is64 = (s_any == 0);

    int warp = tid >> 5, lane = tid & 31;
    int row = blockIdx.x * 8 + warp;
    if (row >= B) return;

    float4 v = *reinterpret_cast<const float4*>(&score[(size_t)row * D + lane * 4]);
    uint32_t p0 = h2_bits(__floats2half2_rn(v.x, v.y));
    uint32_t p1 = h2_bits(__floats2half2_rn(v.z, v.w));
    *reinterpret_cast<uint2*>(&g_h16[(size_t)row * D + lane * 4]) = make_uint2(p0, p1);

    float s = v.x * v.x + v.y * v.y + v.z * v.z + v.w * v.w;
    s += __shfl_xor_sync(0xffffffffu, s, 16);
    s += __shfl_xor_sync(0xffffffffu, s, 8);
    s += __shfl_xor_sync(0xffffffffu, s, 4);
    s += __shfl_xor_sync(0xffffffffu, s, 2);
    s += __shfl_xor_sync(0xffffffffu, s, 1);
    if (lane == 0) {
        g_mag[row] = s;
        g_nes[row] = 0.0f;
        g_lab[row] = is64 ? tw[2 * row] : tw[row];
    }
    if (blockIdx.x == 0 && tid == 0) { g_pcnt = 0; g_tile = 0; }
}

// ---------------- k2: persistent fp16 HMMA Gram, cp.async prefetch --------
#define LDK   136
#define TILEB (128 * LDK * 2)           // 34816 B
#define OFF_A    0
#define OFF_B    (OFF_A + TILEB)
#define OFF_LABA (OFF_B + TILEB)        // [2][128] int
#define OFF_MAGA (OFF_LABA + 1024)      // [2][128] float
#define OFF_LABB (OFF_MAGA + 1024)
#define OFF_MAGB (OFF_LABB + 1024)
#define OFF_CNT  (OFF_MAGB + 1024)
#define OFF_BASE (OFF_CNT + 4)
#define OFF_TN   (OFF_CNT + 8)
#define OFF_PIJ  (OFF_CNT + 16)
#define OFF_PD   (OFF_PIJ + PC * 4)
#define SMEM_SZ  (OFF_PD + PC * 4)

__device__ __forceinline__ void issue_tiles(uint32_t sb, int rb, int cb, int tid) {
    const char* ga = reinterpret_cast<const char*>(&g_h16[(size_t)rb * D]);
    const char* gb = reinterpret_cast<const char*>(&g_h16[(size_t)cb * D]);
#pragma unroll
    for (int it = 0; it < 8; it++) {
        int c = it * 256 + tid;               // 0..2047
        int row = c >> 4, kc = c & 15;
        uint32_t dst = (uint32_t)(row * (LDK * 2) + kc * 16);
        uint32_t src = (uint32_t)(c * 16);    // row*256 + kc*16
        cpa16(sb + OFF_A + dst, ga + src);
        cpa16(sb + OFF_B + dst, gb + src);
    }
}

__global__ __launch_bounds__(256, 2) void k2_mma(const float* __restrict__ alpha_p) {
    extern __shared__ char smem[];
    uint32_t sb = smem_u32(smem);
    int tid = threadIdx.x, wid = tid >> 5, lane = tid & 31;
    int warp_m = wid & 1, warp_n = wid >> 1;

    int* s_labA = reinterpret_cast<int*>(smem + OFF_LABA);
    float* s_magA = reinterpret_cast<float*>(smem + OFF_MAGA);
    int* s_labB = reinterpret_cast<int*>(smem + OFF_LABB);
    float* s_magB = reinterpret_cast<float*>(smem + OFF_MAGB);
    int* s_cnt = reinterpret_cast<int*>(smem + OFF_CNT);
    int* s_base = reinterpret_cast<int*>(smem + OFF_BASE);
    int* s_tn = reinterpret_cast<int*>(smem + OFF_TN);
    int* s_pij = reinterpret_cast<int*>(smem + OFF_PIJ);
    float* s_pd = reinterpret_cast<float*>(smem + OFF_PD);

    float alpha = __ldg(alpha_p);

    if (tid == 0) { *s_cnt = 0; *s_tn = atomicAdd(&g_tile, 1); }
    __syncthreads();
    int t = *s_tn;
    if (t >= NTILE) return;

    int bx, by;
    tile_decode(t, bx, by);
    int rb = by * 128, cb = bx * 128;

    issue_tiles(sb, rb, cb, tid);
    CP_COMMIT();
    if (tid < 128) {
        s_labA[tid] = g_lab[rb + tid];
        s_magA[tid] = g_mag[rb + tid];
        s_labB[tid] = g_lab[cb + tid];
        s_magB[tid] = g_mag[cb + tid];
    }
    CP_WAIT0();
    __syncthreads();

    int buf = 0;
    const uint32_t a_base =
        ((uint32_t)(warp_m * 64 + (lane & 7) + ((lane >> 3) & 1) * 8) * LDK +
         (uint32_t)(lane >> 4) * 8) * 2;
    const uint32_t b_base =
        ((uint32_t)(warp_n * 32 + (lane & 15)) * LDK +
         (uint32_t)(lane >> 4) * 8) * 2;

    while (true) {
        // ---- MMA phase ----
        float acc[4][4][4];
#pragma unroll
        for (int ma = 0; ma < 4; ma++)
#pragma unroll
            for (int na = 0; na < 4; na++)
#pragma unroll
                for (int q = 0; q < 4; q++) acc[ma][na][q] = 0.0f;

        uint32_t sa = sb + OFF_A + a_base;
        uint32_t sB = sb + OFF_B + b_base;
#pragma unroll
        for (int ks = 0; ks < 8; ks++) {
            uint32_t ar[4][4], br[2][4];
#pragma unroll
            for (int ma = 0; ma < 4; ma++)
                LDSM4(ar[ma], sa + (uint32_t)(ma * 16 * LDK + ks * 16) * 2);
#pragma unroll
            for (int nb = 0; nb < 2; nb++)
                LDSM4(br[nb], sB + (uint32_t)(nb * 16 * LDK + ks * 16) * 2);
#pragma unroll
            for (int ma = 0; ma < 4; ma++)
#pragma unroll
                for (int na = 0; na < 4; na++)
                    MMA16816(acc[ma][na], ar[ma], br[na >> 1][na & 1], br[na >> 1][(na & 1) + 2]);
        }
        __syncthreads();   // all warps done reading A/B smem

        // ---- grab next tile, prefetch into A/B smem (dead now) ----
        if (tid == 0) *s_tn = atomicAdd(&g_tile, 1);
        __syncthreads();
        int tn = *s_tn;
        bool have_next = (tn < NTILE);
        int rbn = 0, cbn = 0;
        int nlabA = 0, nlabB = 0;
        float nmagA = 0.0f, nmagB = 0.0f;
        if (have_next) {
            int bxn, byn;
            tile_decode(tn, bxn, byn);
            rbn = byn * 128; cbn = bxn * 128;
            issue_tiles(sb, rbn, cbn, tid);
            CP_COMMIT();
            if (tid < 128) {
                nlabA = g_lab[rbn + tid];
                nmagA = g_mag[rbn + tid];
                nlabB = g_lab[cbn + tid];
                nmagB = g_mag[cbn + tid];
            }
        }

        // ---- epilogue for current tile (overlaps prefetch) ----
        bool offdiag = (rb != cb);
        int ljv[8];
        float mjv[8];
#pragma unroll
        for (int na = 0; na < 4; na++)
#pragma unroll
            for (int q = 0; q < 2; q++) {
                int c = warp_n * 32 + na * 8 + (lane & 3) * 2 + q;
                ljv[na * 2 + q] = s_labB[buf * 128 + c];
                mjv[na * 2 + q] = s_magB[buf * 128 + c];
            }
        float csum[8];
#pragma unroll
        for (int q = 0; q < 8; q++) csum[q] = 0.0f;

#pragma unroll
        for (int ma = 0; ma < 4; ma++) {
#pragma unroll
            for (int h = 0; h < 2; h++) {
                int r = warp_m * 64 + ma * 16 + (lane >> 2) + h * 8;
                float mi = s_magA[buf * 128 + r];
                int li = s_labA[buf * 128 + r];
                float rs = 0.0f;
#pragma unroll
                for (int na = 0; na < 4; na++) {
#pragma unroll
                    for (int q = 0; q < 2; q++) {
                        float dot = acc[ma][na][h * 2 + q];
                        float d2 = fmaf(-2.0f, dot, mi + mjv[na * 2 + q]);
                        float dist = fsqrt_fast(fmaxf(d2, 0.0f));
                        if (li != ljv[na * 2 + q]) {
                            float e = __expf(alpha - dist);
                            rs += e;
                            csum[na * 2 + q] += e;
                        } else {
                            int gi = rb + r;
                            int gj = cb + warp_n * 32 + na * 8 + (lane & 3) * 2 + q;
                            if (offdiag || gi < gj) {
                                int idx = atomicAdd(s_cnt, 1);
                                if (idx < PC) { s_pij[idx] = (gi << 12) | gj; s_pd[idx] = dist; }
                            }
                        }
                    }
                }
                rs += __shfl_xor_sync(0xffffffffu, rs, 1);
                rs += __shfl_xor_sync(0xffffffffu, rs, 2);
                if ((lane & 3) == 0) atomicAdd(&g_nes[rb + r], rs);
            }
        }
        if (offdiag) {
#pragma unroll
            for (int na = 0; na < 4; na++)
#pragma unroll
                for (int q = 0; q < 2; q++) {
                    float v = csum[na * 2 + q];
                    v += __shfl_xor_sync(0xffffffffu, v, 4);
                    v += __shfl_xor_sync(0xffffffffu, v, 8);
                    v += __shfl_xor_sync(0xffffffffu, v, 16);
                    if (lane < 4)
                        atomicAdd(&g_nes[cb + warp_n * 32 + na * 8 + (lane & 3) * 2 + q], v);
                }
        }

        // ---- flush positive pairs ----
        __syncthreads();
        int npair = min(*s_cnt, PC);
        if (tid == 0) *s_base = atomicAdd(&g_pcnt, npair);
        __syncthreads();
        int base = *s_base;
        for (int q = tid; q < npair; q += 256) {
            if (base + q < PCAP) {
                g_pij[base + q] = s_pij[q];
                g_pd[base + q] = s_pd[q];
            }
        }
        if (tid == 0) *s_cnt = 0;

        if (!have_next) break;
        if (tid < 128) {
            s_labA[(buf ^ 1) * 128 + tid] = nlabA;
            s_magA[(buf ^ 1) * 128 + tid] = nmagA;
            s_labB[(buf ^ 1) * 128 + tid] = nlabB;
            s_magB[(buf ^ 1) * 128 + tid] = nmagB;
        }
        CP_WAIT0();
        __syncthreads();
        buf ^= 1;
        rb = rbn; cb = cbn;
    }
}

// ---------------- k3: positive-pair terms, per-block partials -------------
__global__ __launch_bounds__(256) void k3_terms() {
    __shared__ double red[8];
    int n = min(g_pcnt, PCAP);
    double w = 0.0;
    for (int p = blockIdx.x * blockDim.x + threadIdx.x; p < n; p += gridDim.x * blockDim.x) {
        int ij = g_pij[p];
        int i = ij >> 12, j = ij & 4095;
        float l = __logf(g_nes[i] + g_nes[j]) + g_pd[p];
        if (l > 0.0f) w += (double)l * (double)l;
    }
#pragma unroll
    for (int s = 16; s; s >>= 1) w += __shfl_xor_sync(0xffffffffu, w, s);
    int wid = threadIdx.x >> 5;
    if ((threadIdx.x & 31) == 0) red[wid] = w;
    __syncthreads();
    if (threadIdx.x == 0) {
        double t = 0.0;
#pragma unroll
        for (int q = 0; q < 8; q++) t += red[q];
        g_part[blockIdx.x] = t;
    }
}

// ---------------- k4: finalize (counter == number of recorded pairs) ------
__global__ __launch_bounds__(256) void k4_fin(float* out, int nparts) {
    __shared__ double red[8];
    int tid = threadIdx.x;
    double w = (tid < nparts) ? g_part[tid] : 0.0;
#pragma unroll
    for (int s = 16; s; s >>= 1) w += __shfl_xor_sync(0xffffffffu, w, s);
    int wid = tid >> 5;
    if ((tid & 31) == 0) red[wid] = w;
    __syncthreads();
    if (tid == 0) {
        double t = 0.0;
#pragma unroll
        for (int q = 0; q < 8; q++) t += red[q];
        out[0] = (float)(t / (2.0 * (double)g_pcnt));
    }
}

// ---------------- launch ----------------
extern "C" void kernel_launch(void* const* d_in, const int* in_sizes, int n_in,
                              void* d_out, int out_size) {
    const float* score = (const float*)d_in[0];
    const int*   tgt   = (const int*)d_in[1];
    const float* alpha = (const float*)d_in[2];
    float* out = (float*)d_out;
    int B = in_sizes[1];  // 4096

    cudaFuncSetAttribute(k2_mma, cudaFuncAttributeMaxDynamicSharedMemorySize, SMEM_SZ);
    cudaFuncSetAttribute(k2_mma, cudaFuncAttributePreferredSharedMemoryCarveout, 100);

    k1_prep<<<B / 8, 256>>>(score, tgt, B);
    k2_mma<<<NCTA, 256, SMEM_SZ>>>(alpha);
    k3_terms<<<148, 256>>>();
    k4_fin<<<1, 256>>>(out, 148);
}